// round 8
// baseline (speedup 1.0000x reference)
#include <cuda_runtime.h>
#include <cuda_bf16.h>
#include <cstdint>

#define CC 64
#define MAXB 64

// ---------------- device scratch (no allocations allowed) ----------------
__device__ float g_sums[MAXB * CC];
__device__ __align__(16) float g_c[MAXB * CC];        // per-segment fused bias (BN folded)
__device__ __align__(16) uint32_t g_Wfrag[4096];      // B frags: uint4 = {hi_b0, hi_b1, lo_b0, lo_b1}

__device__ __forceinline__ uint32_t smem_u32(const void* p) {
    uint32_t a;
    asm("{ .reg .u64 t; cvta.to.shared.u64 t, %1; cvt.u32.u64 %0, t; }" : "=r"(a) : "l"(p));
    return a;
}

// ---------------- pass 0: zero sums ----------------
__global__ void k_zero(int n) {
    int i = blockIdx.x * blockDim.x + threadIdx.x;
    if (i < n) g_sums[i] = 0.f;
}

// ---------------- pass 1: segment sums (float4, MLP=4, smem tree, few atomics) ----------------
__global__ void k_segsum(const float4* __restrict__ x4, const int* __restrict__ o,
                         int N, int Bseg) {
    __shared__ int so[MAXB];
    __shared__ float4 red[256];
    int t = threadIdx.x;
    if (t < Bseg) so[t] = o[t];
    __syncthreads();
    int c4 = t & 15, rg = t >> 4;
    int rpb = (N + gridDim.x - 1) / gridDim.x;
    int r0 = blockIdx.x * rpb;
    if (r0 >= N) return;
    int r1 = min(N, r0 + rpb);
    int s0 = 0; while (s0 < Bseg - 1 && r0 >= so[s0]) s0++;
    int s1 = s0; while (s1 < Bseg - 1 && (r1 - 1) >= so[s1]) s1++;
    if (s0 == s1) {
        float4 a0 = make_float4(0.f, 0.f, 0.f, 0.f);
        float4 a1 = make_float4(0.f, 0.f, 0.f, 0.f);
        float4 a2 = make_float4(0.f, 0.f, 0.f, 0.f);
        float4 a3 = make_float4(0.f, 0.f, 0.f, 0.f);
        int row = r0 + rg;
        for (; row + 48 < r1; row += 64) {
            float4 v0 = x4[(size_t)row * 16 + c4];
            float4 v1 = x4[(size_t)(row + 16) * 16 + c4];
            float4 v2 = x4[(size_t)(row + 32) * 16 + c4];
            float4 v3 = x4[(size_t)(row + 48) * 16 + c4];
            a0.x += v0.x; a0.y += v0.y; a0.z += v0.z; a0.w += v0.w;
            a1.x += v1.x; a1.y += v1.y; a1.z += v1.z; a1.w += v1.w;
            a2.x += v2.x; a2.y += v2.y; a2.z += v2.z; a2.w += v2.w;
            a3.x += v3.x; a3.y += v3.y; a3.z += v3.z; a3.w += v3.w;
        }
        for (; row < r1; row += 16) {
            float4 v = x4[(size_t)row * 16 + c4];
            a0.x += v.x; a0.y += v.y; a0.z += v.z; a0.w += v.w;
        }
        a0.x += a1.x + a2.x + a3.x; a0.y += a1.y + a2.y + a3.y;
        a0.z += a1.z + a2.z + a3.z; a0.w += a1.w + a2.w + a3.w;
        red[t] = a0;
        __syncthreads();
        #pragma unroll
        for (int s = 8; s >= 1; s >>= 1) {
            if (rg < s) {
                float4 b = red[t + 16 * s];
                float4 a = red[t];
                a.x += b.x; a.y += b.y; a.z += b.z; a.w += b.w;
                red[t] = a;
            }
            __syncthreads();
        }
        if (rg == 0) {
            float4 v = red[t];
            float* dst = &g_sums[s0 * CC + c4 * 4];
            atomicAdd(dst + 0, v.x); atomicAdd(dst + 1, v.y);
            atomicAdd(dst + 2, v.z); atomicAdd(dst + 3, v.w);
        }
    } else {
        int seg = s0;
        float4 a = make_float4(0.f, 0.f, 0.f, 0.f);
        for (int row = r0 + rg; row < r1; row += 16) {
            while (seg < Bseg - 1 && row >= so[seg]) {
                float* dst = &g_sums[seg * CC + c4 * 4];
                atomicAdd(dst + 0, a.x); atomicAdd(dst + 1, a.y);
                atomicAdd(dst + 2, a.z); atomicAdd(dst + 3, a.w);
                a = make_float4(0.f, 0.f, 0.f, 0.f);
                seg++;
            }
            float4 v = x4[(size_t)row * 16 + c4];
            a.x += v.x; a.y += v.y; a.z += v.z; a.w += v.w;
        }
        float* dst = &g_sums[seg * CC + c4 * 4];
        atomicAdd(dst + 0, a.x); atomicAdd(dst + 1, a.y);
        atomicAdd(dst + 2, a.z); atomicAdd(dst + 3, a.w);
    }
}

// ---------------- pass 2 (tiny): MLP on pooled means, fold BN, build B frag image ----------------
__global__ void k_prep(const int* __restrict__ o, const float* __restrict__ W2,
                       const float* __restrict__ b2, const float* __restrict__ W1,
                       const float* __restrict__ b1, const float* __restrict__ gam,
                       const float* __restrict__ bet, const float* __restrict__ rmean,
                       const float* __restrict__ rvar, int Bseg) {
    __shared__ float mean[MAXB * CC];
    __shared__ float h[MAXB * CC];
    __shared__ float ss[CC], st[CC];
    int tid = threadIdx.x;
    if (tid < CC) {
        float sv = gam[tid] * rsqrtf(rvar[tid] + 1e-5f);
        ss[tid] = sv;
        st[tid] = bet[tid] - rmean[tid] * sv;
    }
    for (int i = tid; i < Bseg * CC; i += blockDim.x) {
        int b = i >> 6;
        int cnt = o[b] - (b ? o[b - 1] : 0);
        mean[i] = g_sums[i] / (float)cnt;
    }
    __syncthreads();
    for (int i = tid; i < Bseg * CC; i += blockDim.x) {
        int b = i >> 6, j = i & 63;
        float acc = b2[j];
        #pragma unroll 8
        for (int k = 0; k < CC; k++) acc = fmaf(mean[b * CC + k], W2[k * CC + j], acc);
        h[i] = fmaxf(acc, 0.f);
    }
    __syncthreads();
    // per-segment fused bias: c = (h @ W1_bot + b1) * ss + st
    for (int i = tid; i < Bseg * CC; i += blockDim.x) {
        int b = i >> 6, j = i & 63;
        float acc = b1[j];
        #pragma unroll 8
        for (int k = 0; k < CC; k++) acc = fmaf(h[b * CC + k], W1[(CC + k) * CC + j], acc);
        g_c[i] = acc * ss[j] + st[j];
    }
    // B frag image, uint4-grouped: word i = ((kt*8 + n)*32 + lane)*4 + s
    //   s=0,1: hi pair (bslot 0,1);  s=2,3: lo pair (bslot 0,1)
    //   n_col = n*8 + lane/4,  k2 = kt*16 + (lane&3)*2 + bslot*8
    //   W'[k][n] = W1[k*CC+n]*ss[n]
    for (int i = tid; i < 4096; i += blockDim.x) {
        int s = i & 3;
        int lane = (i >> 2) & 31;
        int grp = i >> 7;
        int n = grp & 7;
        int kt = grp >> 3;
        int bslot = s & 1;
        int n_col = n * 8 + (lane >> 2);
        int k2 = kt * 16 + (lane & 3) * 2 + bslot * 8;
        float sv = ss[n_col];
        float w0 = W1[k2 * CC + n_col] * sv;
        float w1 = W1[(k2 + 1) * CC + n_col] * sv;
        __nv_bfloat162 hp = __floats2bfloat162_rn(w0, w1);
        if (s >= 2) {
            float l0 = w0 - __bfloat162float(hp.x);
            float l1 = w1 - __bfloat162float(hp.y);
            hp = __floats2bfloat162_rn(l0, l1);
        }
        g_Wfrag[i] = *reinterpret_cast<uint32_t*>(&hp);
    }
}

// ---------------- MMA / ldmatrix helpers ----------------
__device__ __forceinline__ void mma16816(float* c, const uint4& a, uint32_t b0, uint32_t b1) {
    asm volatile(
        "mma.sync.aligned.m16n8k16.row.col.f32.bf16.bf16.f32 "
        "{%0,%1,%2,%3}, {%4,%5,%6,%7}, {%8,%9}, {%0,%1,%2,%3};"
        : "+f"(c[0]), "+f"(c[1]), "+f"(c[2]), "+f"(c[3])
        : "r"(a.x), "r"(a.y), "r"(a.z), "r"(a.w), "r"(b0), "r"(b1));
}
__device__ __forceinline__ uint4 ldsm_x4(uint32_t addr) {
    uint4 r;
    asm volatile("ldmatrix.sync.aligned.m8n8.x4.shared.b16 {%0,%1,%2,%3}, [%4];"
        : "=r"(r.x), "=r"(r.y), "=r"(r.z), "=r"(r.w) : "r"(addr));
    return r;
}

// ---------------- pass 3: out = relu(x @ W' + c[seg]) via HMMA 3-term hi/lo split ----------------
// A panels: bf16[128 rows][64 k], 128 B/row, SW128 swizzle. hi at 0, lo at 16384.
struct __align__(1024) SmemM {
    unsigned char A[32768];
    uint4 Bimg[1024];           // 16 KB: {hi_b0, hi_b1, lo_b0, lo_b1} per (kt,n,lane)
    unsigned char segb[128];
};

__global__ __launch_bounds__(256, 4)
void k_main(const float4* __restrict__ x4, const int* __restrict__ o,
            float* __restrict__ out, int N, int Bseg) {
    __shared__ SmemM sm;
    int tid = threadIdx.x;
    int base = blockIdx.x * 128;

    // copy B frag image (coalesced, 16 KB)
    {
        const uint4* src = reinterpret_cast<const uint4*>(g_Wfrag);
        #pragma unroll
        for (int j = 0; j < 4; j++) sm.Bimg[tid + 256 * j] = src[tid + 256 * j];
    }
    // per-row segment ids (removes LDG-latency search from epilogue)
    if (tid < 128) {
        int row = min(base + tid, N - 1);
        int s = 0;
        while (s < Bseg - 1 && row >= __ldg(&o[s])) s++;
        sm.segb[tid] = (unsigned char)s;
    }

    // load x coalesced, convert hi/lo bf16, store row-major swizzled (2x STS.64/thread/iter)
    #pragma unroll
    for (int j = 0; j < 8; j++) {
        int idx = tid + 256 * j;
        int row = idx >> 4, c4 = idx & 15;
        int grow = base + row;
        float4 v = make_float4(0.f, 0.f, 0.f, 0.f);
        if (grow < N) v = x4[(size_t)grow * 16 + c4];

        __nv_bfloat162 h0 = __floats2bfloat162_rn(v.x, v.y);
        __nv_bfloat162 h1 = __floats2bfloat162_rn(v.z, v.w);
        float r0x = v.x - __bfloat162float(h0.x);
        float r0y = v.y - __bfloat162float(h0.y);
        float r1x = v.z - __bfloat162float(h1.x);
        float r1y = v.w - __bfloat162float(h1.y);
        __nv_bfloat162 l0 = __floats2bfloat162_rn(r0x, r0y);
        __nv_bfloat162 l1 = __floats2bfloat162_rn(r1x, r1y);

        uint32_t off = (uint32_t)(row * 128 + ((c4 * 8) ^ ((row & 7) << 4)));
        uint2 hw = make_uint2(*reinterpret_cast<uint32_t*>(&h0), *reinterpret_cast<uint32_t*>(&h1));
        uint2 lw = make_uint2(*reinterpret_cast<uint32_t*>(&l0), *reinterpret_cast<uint32_t*>(&l1));
        *reinterpret_cast<uint2*>(&sm.A[off])         = hw;
        *reinterpret_cast<uint2*>(&sm.A[off + 16384]) = lw;
    }
    __syncthreads();

    int lane = tid & 31, wid = tid >> 5;
    int wm = wid & 3;      // row group: rows wm*32 .. +31
    int wn = wid >> 2;     // col group: cols wn*32 .. +31

    int lm = lane >> 3, lr = lane & 7;
    uint32_t a_base = smem_u32(sm.A);
    uint32_t lane_row = (uint32_t)(wm * 32 + (lm & 1) * 8 + lr) * 128u;

    float acc[2][4][4];
    #pragma unroll
    for (int mb = 0; mb < 2; mb++)
        #pragma unroll
        for (int nt = 0; nt < 4; nt++)
            #pragma unroll
            for (int q = 0; q < 4; q++) acc[mb][nt][q] = 0.f;

    #pragma unroll
    for (int kt = 0; kt < 4; kt++) {
        uint32_t kcol = (uint32_t)((kt * 32 + (lm >> 1) * 16) ^ (lr << 4));
        uint4 ah[2], al[2];
        #pragma unroll
        for (int mb = 0; mb < 2; mb++) {
            uint32_t addr = a_base + lane_row + (uint32_t)(mb * 16 * 128) + kcol;
            ah[mb] = ldsm_x4(addr);
            al[mb] = ldsm_x4(addr + 16384);
        }
        #pragma unroll
        for (int nt = 0; nt < 4; nt++) {
            uint4 bv = sm.Bimg[(kt * 8 + wn * 4 + nt) * 32 + lane];
            #pragma unroll
            for (int mb = 0; mb < 2; mb++) {
                mma16816(acc[mb][nt], ah[mb], bv.x, bv.y);   // hi*hi
                mma16816(acc[mb][nt], ah[mb], bv.z, bv.w);   // hi*lo
                mma16816(acc[mb][nt], al[mb], bv.x, bv.y);   // lo*hi
            }
        }
    }

    // epilogue: bias + relu, direct full-sector STG.64
    int g = lane >> 2, cpair = (lane & 3) * 2;
    #pragma unroll
    for (int mb = 0; mb < 2; mb++) {
        int lr0 = wm * 32 + mb * 16 + g;
        int r0 = base + lr0;
        int r1 = r0 + 8;
        int s0 = sm.segb[lr0];
        int s1 = sm.segb[lr0 + 8];
        #pragma unroll
        for (int nt = 0; nt < 4; nt++) {
            int col = wn * 32 + nt * 8 + cpair;
            float2 bia0 = __ldg(reinterpret_cast<const float2*>(&g_c[s0 * CC + col]));
            float2 bia1 = __ldg(reinterpret_cast<const float2*>(&g_c[s1 * CC + col]));
            if (r0 < N) {
                float2 v;
                v.x = fmaxf(acc[mb][nt][0] + bia0.x, 0.f);
                v.y = fmaxf(acc[mb][nt][1] + bia0.y, 0.f);
                *reinterpret_cast<float2*>(&out[(size_t)r0 * CC + col]) = v;
            }
            if (r1 < N) {
                float2 v;
                v.x = fmaxf(acc[mb][nt][2] + bia1.x, 0.f);
                v.y = fmaxf(acc[mb][nt][3] + bia1.y, 0.f);
                *reinterpret_cast<float2*>(&out[(size_t)r1 * CC + col]) = v;
            }
        }
    }
}

extern "C" void kernel_launch(void* const* d_in, const int* in_sizes, int n_in,
                              void* d_out, int out_size) {
    const float* x     = (const float*)d_in[0];
    const int*   o     = (const int*)  d_in[1];
    const float* W2    = (const float*)d_in[2];
    const float* b2    = (const float*)d_in[3];
    const float* W1    = (const float*)d_in[4];
    const float* b1    = (const float*)d_in[5];
    const float* gam   = (const float*)d_in[6];
    const float* bet   = (const float*)d_in[7];
    const float* rmean = (const float*)d_in[8];
    const float* rvar  = (const float*)d_in[9];
    float* out = (float*)d_out;

    int N = in_sizes[0] / CC;
    int B = in_sizes[1];

    k_zero<<<(B * CC + 255) / 256, 256>>>(B * CC);
    k_segsum<<<4096, 256>>>((const float4*)x, o, N, B);
    k_prep<<<1, 1024>>>(o, W2, b2, W1, b1, gam, bet, rmean, rvar, B);
    k_main<<<(N + 127) / 128, 256>>>((const float4*)x, o, out, N, B);
}

// round 9
// speedup vs baseline: 1.3663x; 1.3663x over previous
#include <cuda_runtime.h>
#include <cuda_bf16.h>
#include <cstdint>

#define CC 64
#define MAXB 64

// ---------------- device scratch (no allocations allowed) ----------------
__device__ float g_sums[MAXB * CC];
__device__ __align__(16) float g_c[MAXB * CC];        // per-segment fused bias (BN folded)
__device__ __align__(16) uint32_t g_Wfrag[4096];      // B frags: uint4 = {hi_b0, hi_b1, lo_b0, lo_b1}

__device__ __forceinline__ uint32_t smem_u32(const void* p) {
    uint32_t a;
    asm("{ .reg .u64 t; cvta.to.shared.u64 t, %1; cvt.u32.u64 %0, t; }" : "=r"(a) : "l"(p));
    return a;
}

// ---------------- pass 0: zero sums ----------------
__global__ void k_zero(int n) {
    int i = blockIdx.x * blockDim.x + threadIdx.x;
    if (i < n) g_sums[i] = 0.f;
}

// ---------------- pass 1: segment sums (float4, MLP=4, smem tree, few atomics) ----------------
__global__ void k_segsum(const float4* __restrict__ x4, const int* __restrict__ o,
                         int N, int Bseg) {
    __shared__ int so[MAXB];
    __shared__ float4 red[256];
    int t = threadIdx.x;
    if (t < Bseg) so[t] = o[t];
    __syncthreads();
    int c4 = t & 15, rg = t >> 4;
    int rpb = (N + gridDim.x - 1) / gridDim.x;
    int r0 = blockIdx.x * rpb;
    if (r0 >= N) return;
    int r1 = min(N, r0 + rpb);
    int s0 = 0; while (s0 < Bseg - 1 && r0 >= so[s0]) s0++;
    int s1 = s0; while (s1 < Bseg - 1 && (r1 - 1) >= so[s1]) s1++;
    if (s0 == s1) {
        float4 a0 = make_float4(0.f, 0.f, 0.f, 0.f);
        float4 a1 = make_float4(0.f, 0.f, 0.f, 0.f);
        float4 a2 = make_float4(0.f, 0.f, 0.f, 0.f);
        float4 a3 = make_float4(0.f, 0.f, 0.f, 0.f);
        int row = r0 + rg;
        for (; row + 48 < r1; row += 64) {
            float4 v0 = x4[(size_t)row * 16 + c4];
            float4 v1 = x4[(size_t)(row + 16) * 16 + c4];
            float4 v2 = x4[(size_t)(row + 32) * 16 + c4];
            float4 v3 = x4[(size_t)(row + 48) * 16 + c4];
            a0.x += v0.x; a0.y += v0.y; a0.z += v0.z; a0.w += v0.w;
            a1.x += v1.x; a1.y += v1.y; a1.z += v1.z; a1.w += v1.w;
            a2.x += v2.x; a2.y += v2.y; a2.z += v2.z; a2.w += v2.w;
            a3.x += v3.x; a3.y += v3.y; a3.z += v3.z; a3.w += v3.w;
        }
        for (; row < r1; row += 16) {
            float4 v = x4[(size_t)row * 16 + c4];
            a0.x += v.x; a0.y += v.y; a0.z += v.z; a0.w += v.w;
        }
        a0.x += a1.x + a2.x + a3.x; a0.y += a1.y + a2.y + a3.y;
        a0.z += a1.z + a2.z + a3.z; a0.w += a1.w + a2.w + a3.w;
        red[t] = a0;
        __syncthreads();
        #pragma unroll
        for (int s = 8; s >= 1; s >>= 1) {
            if (rg < s) {
                float4 b = red[t + 16 * s];
                float4 a = red[t];
                a.x += b.x; a.y += b.y; a.z += b.z; a.w += b.w;
                red[t] = a;
            }
            __syncthreads();
        }
        if (rg == 0) {
            float4 v = red[t];
            float* dst = &g_sums[s0 * CC + c4 * 4];
            atomicAdd(dst + 0, v.x); atomicAdd(dst + 1, v.y);
            atomicAdd(dst + 2, v.z); atomicAdd(dst + 3, v.w);
        }
    } else {
        int seg = s0;
        float4 a = make_float4(0.f, 0.f, 0.f, 0.f);
        for (int row = r0 + rg; row < r1; row += 16) {
            while (seg < Bseg - 1 && row >= so[seg]) {
                float* dst = &g_sums[seg * CC + c4 * 4];
                atomicAdd(dst + 0, a.x); atomicAdd(dst + 1, a.y);
                atomicAdd(dst + 2, a.z); atomicAdd(dst + 3, a.w);
                a = make_float4(0.f, 0.f, 0.f, 0.f);
                seg++;
            }
            float4 v = x4[(size_t)row * 16 + c4];
            a.x += v.x; a.y += v.y; a.z += v.z; a.w += v.w;
        }
        float* dst = &g_sums[seg * CC + c4 * 4];
        atomicAdd(dst + 0, a.x); atomicAdd(dst + 1, a.y);
        atomicAdd(dst + 2, a.z); atomicAdd(dst + 3, a.w);
    }
}

// ---------------- pass 2 (tiny): MLP on pooled means, fold BN, build B frag image ----------------
__global__ void k_prep(const int* __restrict__ o, const float* __restrict__ W2,
                       const float* __restrict__ b2, const float* __restrict__ W1,
                       const float* __restrict__ b1, const float* __restrict__ gam,
                       const float* __restrict__ bet, const float* __restrict__ rmean,
                       const float* __restrict__ rvar, int Bseg) {
    __shared__ float mean[MAXB * CC];
    __shared__ float h[MAXB * CC];
    __shared__ float ss[CC], st[CC];
    int tid = threadIdx.x;
    if (tid < CC) {
        float sv = gam[tid] * rsqrtf(rvar[tid] + 1e-5f);
        ss[tid] = sv;
        st[tid] = bet[tid] - rmean[tid] * sv;
    }
    for (int i = tid; i < Bseg * CC; i += blockDim.x) {
        int b = i >> 6;
        int cnt = o[b] - (b ? o[b - 1] : 0);
        mean[i] = g_sums[i] / (float)cnt;
    }
    __syncthreads();
    for (int i = tid; i < Bseg * CC; i += blockDim.x) {
        int b = i >> 6, j = i & 63;
        float acc = b2[j];
        #pragma unroll 8
        for (int k = 0; k < CC; k++) acc = fmaf(mean[b * CC + k], W2[k * CC + j], acc);
        h[i] = fmaxf(acc, 0.f);
    }
    __syncthreads();
    // per-segment fused bias: c = (h @ W1_bot + b1) * ss + st
    for (int i = tid; i < Bseg * CC; i += blockDim.x) {
        int b = i >> 6, j = i & 63;
        float acc = b1[j];
        #pragma unroll 8
        for (int k = 0; k < CC; k++) acc = fmaf(h[b * CC + k], W1[(CC + k) * CC + j], acc);
        g_c[i] = acc * ss[j] + st[j];
    }
    // B frag image, uint4-grouped: word i = ((kt*8 + n)*32 + lane)*4 + s
    //   s=0,1: hi pair (bslot 0,1);  s=2,3: lo pair (bslot 0,1)
    //   frag col f = lane>>2, column PERMUTED for stmatrix-natural staging:
    //     n_col = n*8 + (f>>1) + (f&1)*4
    //   k2 = kt*16 + (lane&3)*2 + bslot*8;  W'[k][n] = W1[k*CC+n]*ss[n]
    for (int i = tid; i < 4096; i += blockDim.x) {
        int s = i & 3;
        int lane = (i >> 2) & 31;
        int grp = i >> 7;
        int n = grp & 7;
        int kt = grp >> 3;
        int bslot = s & 1;
        int f = lane >> 2;
        int n_col = n * 8 + (f >> 1) + ((f & 1) << 2);
        int k2 = kt * 16 + (lane & 3) * 2 + bslot * 8;
        float sv = ss[n_col];
        float w0 = W1[k2 * CC + n_col] * sv;
        float w1 = W1[(k2 + 1) * CC + n_col] * sv;
        __nv_bfloat162 hp = __floats2bfloat162_rn(w0, w1);
        if (s >= 2) {
            float l0 = w0 - __bfloat162float(hp.x);
            float l1 = w1 - __bfloat162float(hp.y);
            hp = __floats2bfloat162_rn(l0, l1);
        }
        g_Wfrag[i] = *reinterpret_cast<uint32_t*>(&hp);
    }
}

// ---------------- MMA / ldmatrix / stmatrix helpers ----------------
__device__ __forceinline__ void mma16816(float* c, const uint4& a, uint32_t b0, uint32_t b1) {
    asm volatile(
        "mma.sync.aligned.m16n8k16.row.col.f32.bf16.bf16.f32 "
        "{%0,%1,%2,%3}, {%4,%5,%6,%7}, {%8,%9}, {%0,%1,%2,%3};"
        : "+f"(c[0]), "+f"(c[1]), "+f"(c[2]), "+f"(c[3])
        : "r"(a.x), "r"(a.y), "r"(a.z), "r"(a.w), "r"(b0), "r"(b1));
}
__device__ __forceinline__ uint4 ldsm_x4(uint32_t addr) {
    uint4 r;
    asm volatile("ldmatrix.sync.aligned.m8n8.x4.shared.b16 {%0,%1,%2,%3}, [%4];"
        : "=r"(r.x), "=r"(r.y), "=r"(r.z), "=r"(r.w) : "r"(addr));
    return r;
}
__device__ __forceinline__ void stsm_x4(uint32_t addr, uint32_t r0, uint32_t r1,
                                        uint32_t r2, uint32_t r3) {
    asm volatile("stmatrix.sync.aligned.m8n8.x4.shared.b16 [%0], {%1,%2,%3,%4};"
        :: "r"(addr), "r"(r0), "r"(r1), "r"(r2), "r"(r3) : "memory");
}

// ---------------- pass 3: out = relu(x @ W' + c[seg]) via HMMA 3-term hi/lo split ----------------
// A panels: bf16[128 rows][64 k], 128 B/row, SW128 swizzle. hi at 0, lo at 16384.
// After the MMA loop, A region is reused as fp32 output stage: 128 rows x 256 B,
// 16B chunk at (row, c16) stored at byte row*256 + ((c16*16) ^ ((row&7)<<4)).
struct __align__(1024) SmemM {
    unsigned char A[32768];
    uint4 Bimg[1024];           // 16 KB: {hi_b0, hi_b1, lo_b0, lo_b1} per (kt,n,lane)
    unsigned char segb[128];
};

__global__ __launch_bounds__(256)
void k_main(const float4* __restrict__ x4, const int* __restrict__ o,
            float* __restrict__ out, int N, int Bseg) {
    __shared__ SmemM sm;
    int tid = threadIdx.x;
    int base = blockIdx.x * 128;

    // copy B frag image (coalesced, 16 KB)
    {
        const uint4* src = reinterpret_cast<const uint4*>(g_Wfrag);
        #pragma unroll
        for (int j = 0; j < 4; j++) sm.Bimg[tid + 256 * j] = src[tid + 256 * j];
    }
    // per-row segment ids
    if (tid < 128) {
        int row = min(base + tid, N - 1);
        int s = 0;
        while (s < Bseg - 1 && row >= __ldg(&o[s])) s++;
        sm.segb[tid] = (unsigned char)s;
    }

    // load x coalesced, convert hi/lo bf16, store row-major swizzled (2x STS.64/thread/iter)
    #pragma unroll
    for (int j = 0; j < 8; j++) {
        int idx = tid + 256 * j;
        int row = idx >> 4, c4 = idx & 15;
        int grow = base + row;
        float4 v = make_float4(0.f, 0.f, 0.f, 0.f);
        if (grow < N) v = x4[(size_t)grow * 16 + c4];

        __nv_bfloat162 h0 = __floats2bfloat162_rn(v.x, v.y);
        __nv_bfloat162 h1 = __floats2bfloat162_rn(v.z, v.w);
        float r0x = v.x - __bfloat162float(h0.x);
        float r0y = v.y - __bfloat162float(h0.y);
        float r1x = v.z - __bfloat162float(h1.x);
        float r1y = v.w - __bfloat162float(h1.y);
        __nv_bfloat162 l0 = __floats2bfloat162_rn(r0x, r0y);
        __nv_bfloat162 l1 = __floats2bfloat162_rn(r1x, r1y);

        uint32_t off = (uint32_t)(row * 128 + ((c4 * 8) ^ ((row & 7) << 4)));
        uint2 hw = make_uint2(*reinterpret_cast<uint32_t*>(&h0), *reinterpret_cast<uint32_t*>(&h1));
        uint2 lw = make_uint2(*reinterpret_cast<uint32_t*>(&l0), *reinterpret_cast<uint32_t*>(&l1));
        *reinterpret_cast<uint2*>(&sm.A[off])         = hw;
        *reinterpret_cast<uint2*>(&sm.A[off + 16384]) = lw;
    }
    __syncthreads();

    int lane = tid & 31, wid = tid >> 5;
    int wm = wid & 3;      // row group: rows wm*32 .. +31
    int wn = wid >> 2;     // col group: cols wn*32 .. +31

    int lm = lane >> 3, lr = lane & 7;
    uint32_t a_base = smem_u32(sm.A);
    uint32_t lane_row = (uint32_t)(wm * 32 + (lm & 1) * 8 + lr) * 128u;

    float acc[2][4][4];
    #pragma unroll
    for (int mb = 0; mb < 2; mb++)
        #pragma unroll
        for (int nt = 0; nt < 4; nt++)
            #pragma unroll
            for (int q = 0; q < 4; q++) acc[mb][nt][q] = 0.f;

    #pragma unroll
    for (int kt = 0; kt < 4; kt++) {
        uint32_t kcol = (uint32_t)((kt * 32 + (lm >> 1) * 16) ^ (lr << 4));
        uint4 ah[2], al[2];
        #pragma unroll
        for (int mb = 0; mb < 2; mb++) {
            uint32_t addr = a_base + lane_row + (uint32_t)(mb * 16 * 128) + kcol;
            ah[mb] = ldsm_x4(addr);
            al[mb] = ldsm_x4(addr + 16384);
        }
        #pragma unroll
        for (int nt = 0; nt < 4; nt++) {
            uint4 bv = sm.Bimg[(kt * 8 + wn * 4 + nt) * 32 + lane];
            #pragma unroll
            for (int mb = 0; mb < 2; mb++) {
                mma16816(acc[mb][nt], ah[mb], bv.x, bv.y);   // hi*hi
                mma16816(acc[mb][nt], ah[mb], bv.z, bv.w);   // hi*lo
                mma16816(acc[mb][nt], al[mb], bv.x, bv.y);   // lo*hi
            }
        }
    }
    __syncthreads();   // all warps done reading A panels

    // stage accumulators via stmatrix.x4 (column-permuted B makes this row-natural)
    {
        int m = lane >> 3, rl8 = lane & 7;
        #pragma unroll
        for (int mb = 0; mb < 2; mb++) {
            int rrow = wm * 32 + mb * 16 + ((m & 1) << 3) + rl8;
            uint32_t rowb = a_base + (uint32_t)(rrow * 256);
            #pragma unroll
            for (int nt = 0; nt < 4; nt++) {
                int ci = wn * 8 + nt * 2 + (m >> 1);
                uint32_t addr = rowb + (uint32_t)((ci * 16) ^ (rl8 << 4));
                stsm_x4(addr,
                        __float_as_uint(acc[mb][nt][0]), __float_as_uint(acc[mb][nt][2]),
                        __float_as_uint(acc[mb][nt][1]), __float_as_uint(acc[mb][nt][3]));
            }
        }
    }
    __syncthreads();

    // read stage, add bias, relu, coalesced STG.128
    float4* out4 = reinterpret_cast<float4*>(out);
    #pragma unroll
    for (int j = 0; j < 8; j++) {
        int idx = tid + 256 * j;
        int row = idx >> 4, c4 = idx & 15;
        int grow = base + row;
        if (grow < N) {
            const float4 v = *reinterpret_cast<const float4*>(
                &sm.A[row * 256 + ((c4 * 16) ^ ((row & 7) << 4))]);
            int seg = sm.segb[row];
            float4 b = __ldg(reinterpret_cast<const float4*>(&g_c[seg * CC + c4 * 4]));
            float4 r;
            r.x = fmaxf(v.x + b.x, 0.f);
            r.y = fmaxf(v.y + b.y, 0.f);
            r.z = fmaxf(v.z + b.z, 0.f);
            r.w = fmaxf(v.w + b.w, 0.f);
            out4[(size_t)grow * 16 + c4] = r;
        }
    }
}

extern "C" void kernel_launch(void* const* d_in, const int* in_sizes, int n_in,
                              void* d_out, int out_size) {
    const float* x     = (const float*)d_in[0];
    const int*   o     = (const int*)  d_in[1];
    const float* W2    = (const float*)d_in[2];
    const float* b2    = (const float*)d_in[3];
    const float* W1    = (const float*)d_in[4];
    const float* b1    = (const float*)d_in[5];
    const float* gam   = (const float*)d_in[6];
    const float* bet   = (const float*)d_in[7];
    const float* rmean = (const float*)d_in[8];
    const float* rvar  = (const float*)d_in[9];
    float* out = (float*)d_out;

    int N = in_sizes[0] / CC;
    int B = in_sizes[1];

    k_zero<<<(B * CC + 255) / 256, 256>>>(B * CC);
    k_segsum<<<4096, 256>>>((const float4*)x, o, N, B);
    k_prep<<<1, 1024>>>(o, W2, b2, W1, b1, gam, bet, rmean, rvar, B);
    k_main<<<(N + 127) / 128, 256>>>((const float4*)x, o, out, N, B);
}